// round 6
// baseline (speedup 1.0000x reference)
#include <cuda_runtime.h>
#include <cstdint>
#include <math.h>

#define NB 128
#define NTOK 577
#define NP 576
#define DD 768
#define NG 17
#define NGC 18          // 17 groups + cls row
#define NOCC 10

typedef unsigned long long ull;

// ---- packed f32x2 helpers (sm_103a) ----
__device__ __forceinline__ ull pk2(float a, float b) {
    ull r; asm("mov.b64 %0, {%1,%2};" : "=l"(r) : "f"(a), "f"(b)); return r;
}
__device__ __forceinline__ void fma2(ull &acc, ull a, ull b) {
    asm("fma.rn.f32x2 %0, %1, %2, %0;" : "+l"(acc) : "l"(a), "l"(b));
}
__device__ __forceinline__ float hadd2(ull a) {
    return __uint_as_float((unsigned)a) + __uint_as_float((unsigned)(a >> 32));
}
__device__ __forceinline__ void cpasync16(uint32_t dst, const void* src) {
    asm volatile("cp.async.cg.shared.global [%0], [%1], 16;"
                 :: "r"(dst), "l"(src) : "memory");
}

// scratch (device globals; no allocation)
__device__ float g_scores[(size_t)NB * NG * NP];   // raw scores from K1
__device__ float g_sim[(size_t)NB * NP];

// ============================ K1: scores + sim ============================
// 576 threads (18 warps). Warp w owns patches [32w, 32w+32).
// Lane: li = ln&15, h = ln>>4. Thread computes patches p0=32w+li, p1=p0+16
// for groups [9h, 9h+9) (group 17 = cls row). x staged per-warp via cp.async.
#define K1_THREADS 576
#define TILE_D 32
#define NT (DD / TILE_D)            // 24
#define PITCH 36                    // floats/row: conflict-free LDS.128
#define TILE_FLOATS (32 * PITCH)    // 1152
#define WPITCH 772                  // W row pitch: 9*772*4 % 128 = 16 (bank-split)
#define OFF_W  (18 * 2 * TILE_FLOATS)          // 41472
#define OFF_CD (OFF_W + NGC * WPITCH)          // 41472 + 13896 = 55368
#define K1_SMEM_FLOATS (OFF_CD + NP)           // 55944 floats = 223776 B

extern __shared__ float sm1[];

__global__ void __launch_bounds__(K1_THREADS, 1)
k1_scores(const float* __restrict__ x, const float* __restrict__ gw) {
    const int b   = blockIdx.x;
    const int tid = threadIdx.x;
    const int w   = tid >> 5, ln = tid & 31;
    const int li  = ln & 15,  h  = ln >> 4;
    float* s_w  = sm1 + OFF_W;
    float* s_cd = sm1 + OFF_CD;

    const size_t xb = (size_t)b * NTOK * DD;

    // stage W^T ([g][d], pitch 772) + cls as row 17
    for (int i = tid; i < DD * NG; i += K1_THREADS) {
        int d = i / NG, g = i % NG;
        s_w[g * WPITCH + d] = gw[i];
    }
    for (int i = tid; i < DD; i += K1_THREADS) s_w[NG * WPITCH + i] = x[xb + i];

    const uint32_t smem_base = (uint32_t)__cvta_generic_to_shared(sm1);
    const uint32_t buf0 = smem_base + (uint32_t)(w * 2) * TILE_FLOATS * 4;
    const uint32_t buf1 = buf0 + TILE_FLOATS * 4;
    const float* xrow = x + xb + DD + (size_t)(w * 32) * DD;  // token 1+32w

    // prologue: issue tiles 0 and 1 (8 cp.async of 16B per lane per tile)
#pragma unroll
    for (int t = 0; t < 2; ++t) {
        uint32_t dst = t ? buf1 : buf0;
        const float* src = xrow + t * TILE_D;
#pragma unroll
        for (int k = 0; k < 8; ++k) {
            int idx = ln + 32 * k;
            int row = idx >> 3, ch = idx & 7;
            cpasync16(dst + (uint32_t)(row * PITCH + ch * 4) * 4,
                      src + (size_t)row * DD + ch * 4);
        }
        asm volatile("cp.async.commit_group;" ::: "memory");
    }
    __syncthreads();   // W ready

    ull a0[9], a1[9], nr0 = 0, nr1 = 0;
#pragma unroll
    for (int g = 0; g < 9; ++g) { a0[g] = 0; a1[g] = 0; }

    const float* wbase = s_w + h * 9 * WPITCH;

    for (int t = 0; t < NT; ++t) {
        asm volatile("cp.async.wait_group 1;" ::: "memory");
        __syncwarp();
        const float* xt  = sm1 + (size_t)(w * 2 + (t & 1)) * TILE_FLOATS;
        const float* wd0 = wbase + t * TILE_D;
#pragma unroll
        for (int blk = 0; blk < 8; ++blk) {
            ulonglong2 xv0 = *reinterpret_cast<const ulonglong2*>(
                xt + li * PITCH + blk * 4);
            ulonglong2 xv1 = *reinterpret_cast<const ulonglong2*>(
                xt + (li + 16) * PITCH + blk * 4);
            const float* wdb = wd0 + blk * 4;
#pragma unroll
            for (int gi = 0; gi < 9; ++gi) {
                ulonglong2 wv = *reinterpret_cast<const ulonglong2*>(wdb + gi * WPITCH);
                fma2(a0[gi], xv0.x, wv.x); fma2(a0[gi], xv0.y, wv.y);
                fma2(a1[gi], xv1.x, wv.x); fma2(a1[gi], xv1.y, wv.y);
            }
            fma2(nr0, xv0.x, xv0.x); fma2(nr0, xv0.y, xv0.y);
            fma2(nr1, xv1.x, xv1.x); fma2(nr1, xv1.y, xv1.y);
        }
        __syncwarp();
        if (t + 2 < NT) {
            uint32_t dst = (t & 1) ? buf1 : buf0;
            const float* src = xrow + (t + 2) * TILE_D;
#pragma unroll
            for (int k = 0; k < 8; ++k) {
                int idx = ln + 32 * k;
                int row = idx >> 3, ch = idx & 7;
                cpasync16(dst + (uint32_t)(row * PITCH + ch * 4) * 4,
                          src + (size_t)row * DD + ch * 4);
            }
        }
        asm volatile("cp.async.commit_group;" ::: "memory");
    }

    const int p0 = w * 32 + li, p1 = p0 + 16;
#pragma unroll
    for (int gi = 0; gi < 9; ++gi) {
        int g = h * 9 + gi;
        float v0 = hadd2(a0[gi]), v1 = hadd2(a1[gi]);
        if (g < NG) {
            g_scores[((size_t)b * NG + g) * NP + p0] = v0;
            g_scores[((size_t)b * NG + g) * NP + p1] = v1;
        } else {            // g == 17: cls dot-product
            s_cd[p0] = v0;
            s_cd[p1] = v1;
        }
    }
    __syncthreads();
    if (h == 0) {
        // cls-norm factor dropped: positive per-batch constant, ordering-invariant
        g_sim[(size_t)b * NP + p0] = s_cd[p0] / fmaxf(sqrtf(hadd2(nr0)), 1e-12f);
        g_sim[(size_t)b * NP + p1] = s_cd[p1] / fmaxf(sqrtf(hadd2(nr1)), 1e-12f);
    }
}

// ========= K3: fused topk + softmax + attn out + group features ==========
// grid (NB, 3), 256 threads. Column d = by*256+tid. Each CTA redundantly
// computes topk+softmax (cheap, inputs already needed); y==0 writes attn.
#define K3_SMEM_FLOATS (NG * NP + 2 * NP)   // 9792 + 1152 = 10944 (43776 B)

extern __shared__ float sm3[];

__global__ void __launch_bounds__(256, 2)
k3_fused(const float* __restrict__ x, float* __restrict__ out) {
    const int b   = blockIdx.x;
    const int by  = blockIdx.y;
    const int tid = threadIdx.x;
    const int d   = by * 256 + tid;
    float* s_at   = sm3;
    float* s_sim  = sm3 + NG * NP;
    float* s_mask = s_sim + NP;

    for (int i = tid; i < NP; i += 256) {
        s_sim[i]  = g_sim[(size_t)b * NP + i];
        s_mask[i] = 1.0f;
    }
    __syncthreads();

    // topk: 10x argmin in warp 0 (tie -> lower index)
    if (tid < 32) {
        for (int k = 0; k < NOCC; ++k) {
            float best = 3.4e38f; int bi = NP;
#pragma unroll
            for (int q = 0; q < NP / 32; ++q) {
                int idx = tid + q * 32;
                float v = s_sim[idx];
                if (v < best || (v == best && idx < bi)) { best = v; bi = idx; }
            }
#pragma unroll
            for (int off = 16; off; off >>= 1) {
                float ov = __shfl_down_sync(0xffffffffu, best, off);
                int   oi = __shfl_down_sync(0xffffffffu, bi, off);
                if (ov < best || (ov == best && oi < bi)) { best = ov; bi = oi; }
            }
            bi = __shfl_sync(0xffffffffu, bi, 0);
            if (tid == 0) { s_sim[bi] = 3.4e38f; s_mask[bi] = 0.0f; }
            __syncwarp();
        }
    }
    __syncthreads();

    // softmax over g -> s_at (masked) and attn output (y==0 only)
    float* oat = out + (size_t)NB * NGC * DD + (size_t)b * NG * NP;
    for (int p = tid; p < NP; p += 256) {
        const float mk = s_mask[p];
        float tv[NG];
        float m = -3.4e38f;
#pragma unroll
        for (int g = 0; g < NG; ++g) {
            tv[g] = g_scores[((size_t)b * NG + g) * NP + p] * 10.0f;
            m = fmaxf(m, tv[g]);
        }
        float ssum = 0.f;
#pragma unroll
        for (int g = 0; g < NG; ++g) { tv[g] = __expf(tv[g] - m); ssum += tv[g]; }
        const float inv = 1.0f / ssum;
#pragma unroll
        for (int g = 0; g < NG; ++g) {
            float a = tv[g] * inv;
            if (by == 0) oat[g * NP + p] = (mk != 0.f) ? a : (1.0f / 17.0f);
            s_at[g * NP + p] = (mk != 0.f) ? a : 0.f;
        }
    }
    __syncthreads();

    // features GEMM: acc over patches, column d per thread
    const size_t xb = (size_t)b * NTOK * DD;
    const float* xp = x + xb + DD + d;
    ull acc[NG];
#pragma unroll
    for (int g = 0; g < NG; ++g) acc[g] = 0ull;

    float A0 = xp[0], A1 = xp[(size_t)1 * DD], A2 = xp[(size_t)2 * DD], A3 = xp[(size_t)3 * DD];
    float B0 = xp[(size_t)4 * DD], B1 = xp[(size_t)5 * DD], B2 = xp[(size_t)6 * DD], B3 = xp[(size_t)7 * DD];

#pragma unroll 2
    for (int s = 0; s < NP / 4; ++s) {
        float c0, c1, c2, c3;
        if ((s & 1) == 0) {
            c0 = A0; c1 = A1; c2 = A2; c3 = A3;
            if (s + 2 < NP / 4) {
                A0 = xp[(size_t)(4 * s +  8) * DD]; A1 = xp[(size_t)(4 * s +  9) * DD];
                A2 = xp[(size_t)(4 * s + 10) * DD]; A3 = xp[(size_t)(4 * s + 11) * DD];
            }
        } else {
            c0 = B0; c1 = B1; c2 = B2; c3 = B3;
            if (s + 2 < NP / 4) {
                B0 = xp[(size_t)(4 * s +  8) * DD]; B1 = xp[(size_t)(4 * s +  9) * DD];
                B2 = xp[(size_t)(4 * s + 10) * DD]; B3 = xp[(size_t)(4 * s + 11) * DD];
            }
        }
        ull x01 = pk2(c0, c1), x23 = pk2(c2, c3);
        const float* ap = s_at + 4 * s;
#pragma unroll
        for (int g = 0; g < NG; ++g) {
            ulonglong2 at = *reinterpret_cast<const ulonglong2*>(ap + g * NP);
            fma2(acc[g], x01, at.x);
            fma2(acc[g], x23, at.y);
        }
    }

    float* ob = out + (size_t)b * NGC * DD;
    ob[d] = x[xb + d];                        // feats[b][0][d] = cls
#pragma unroll
    for (int g = 0; g < NG; ++g)
        ob[(size_t)(1 + g) * DD + d] = hadd2(acc[g]);
}

extern "C" void kernel_launch(void* const* d_in, const int* in_sizes, int n_in,
                              void* d_out, int out_size) {
    const float* x  = (const float*)d_in[0];
    const float* gw = (const float*)d_in[1];
    float* out = (float*)d_out;

    static bool inited = false;
    if (!inited) {
        cudaFuncSetAttribute(k1_scores, cudaFuncAttributeMaxDynamicSharedMemorySize,
                             K1_SMEM_FLOATS * 4);
        cudaFuncSetAttribute(k3_fused, cudaFuncAttributeMaxDynamicSharedMemorySize,
                             K3_SMEM_FLOATS * 4);
        inited = true;
    }

    k1_scores<<<NB, K1_THREADS, K1_SMEM_FLOATS * 4>>>(x, gw);
    k3_fused<<<dim3(NB, 3), 256, K3_SMEM_FLOATS * 4>>>(x, out);
}

// round 7
// speedup vs baseline: 1.1656x; 1.1656x over previous
#include <cuda_runtime.h>
#include <cstdint>
#include <math.h>

#define NB 128
#define NTOK 577
#define NP 576
#define DD 768
#define NG 17
#define NGC 18          // 17 groups + cls row
#define NOCC 10

typedef unsigned long long ull;

// ---- packed f32x2 helpers (sm_103a) ----
__device__ __forceinline__ ull pk2(float a, float b) {
    ull r; asm("mov.b64 %0, {%1,%2};" : "=l"(r) : "f"(a), "f"(b)); return r;
}
__device__ __forceinline__ void fma2(ull &acc, ull a, ull b) {
    asm("fma.rn.f32x2 %0, %1, %2, %0;" : "+l"(acc) : "l"(a), "l"(b));
}
__device__ __forceinline__ float hadd2(ull a) {
    return __uint_as_float((unsigned)a) + __uint_as_float((unsigned)(a >> 32));
}
__device__ __forceinline__ void cpasync16(uint32_t dst, const void* src) {
    asm volatile("cp.async.cg.shared.global [%0], [%1], 16;"
                 :: "r"(dst), "l"(src) : "memory");
}

// scratch (device global; no allocation). Holds MASKED attn after K1.
__device__ float g_scores[(size_t)NB * NG * NP];

// ================= K1: scores + sim + topk + softmax + attn ===============
// 576 threads (18 warps). Warp w owns patches [32w, 32w+32).
// Lane: li = ln&15, h = ln>>4. Thread computes patches p0=32w+li, p1=p0+16
// for groups [9h, 9h+9) (group 17 = cls row). x staged per-warp via cp.async.
// Epilogue: scores -> smem, warp-0 topk, per-patch softmax, write attn out
// + masked attn to g_scores.
#define K1_THREADS 576
#define TILE_D 32
#define NT (DD / TILE_D)            // 24
#define PITCH 36                    // floats/row: conflict-free LDS.128
#define TILE_FLOATS (32 * PITCH)    // 1152
#define WPITCH 772                  // W row pitch: 9*772*4 % 128 = 16 (bank-split)
#define OFF_W  (18 * 2 * TILE_FLOATS)          // 41472
#define OFF_CD (OFF_W + NGC * WPITCH)          // 41472 + 13896 = 55368
#define K1_SMEM_FLOATS (OFF_CD + NP)           // 55944 floats = 223776 B
// epilogue aliases (tile region is dead): s_sc[17*576], s_sim[576], s_mask[576]

extern __shared__ float sm1[];

__global__ void __launch_bounds__(K1_THREADS, 1)
k1_scores(const float* __restrict__ x, const float* __restrict__ gw,
          float* __restrict__ out) {
    const int b   = blockIdx.x;
    const int tid = threadIdx.x;
    const int w   = tid >> 5, ln = tid & 31;
    const int li  = ln & 15,  h  = ln >> 4;
    float* s_w  = sm1 + OFF_W;
    float* s_cd = sm1 + OFF_CD;

    const size_t xb = (size_t)b * NTOK * DD;

    // stage W^T ([g][d], pitch 772) + cls as row 17
    for (int i = tid; i < DD * NG; i += K1_THREADS) {
        int d = i / NG, g = i % NG;
        s_w[g * WPITCH + d] = gw[i];
    }
    for (int i = tid; i < DD; i += K1_THREADS) s_w[NG * WPITCH + i] = x[xb + i];

    const uint32_t smem_base = (uint32_t)__cvta_generic_to_shared(sm1);
    const uint32_t buf0 = smem_base + (uint32_t)(w * 2) * TILE_FLOATS * 4;
    const uint32_t buf1 = buf0 + TILE_FLOATS * 4;
    const float* xrow = x + xb + DD + (size_t)(w * 32) * DD;  // token 1+32w

    // prologue: issue tiles 0 and 1
#pragma unroll
    for (int t = 0; t < 2; ++t) {
        uint32_t dst = t ? buf1 : buf0;
        const float* src = xrow + t * TILE_D;
#pragma unroll
        for (int k = 0; k < 8; ++k) {
            int idx = ln + 32 * k;
            int row = idx >> 3, ch = idx & 7;
            cpasync16(dst + (uint32_t)(row * PITCH + ch * 4) * 4,
                      src + (size_t)row * DD + ch * 4);
        }
        asm volatile("cp.async.commit_group;" ::: "memory");
    }
    __syncthreads();   // W ready

    ull a0[9], a1[9], nr0 = 0, nr1 = 0;
#pragma unroll
    for (int g = 0; g < 9; ++g) { a0[g] = 0; a1[g] = 0; }

    const float* wbase = s_w + h * 9 * WPITCH;

    for (int t = 0; t < NT; ++t) {
        asm volatile("cp.async.wait_group 1;" ::: "memory");
        __syncwarp();
        const float* xt  = sm1 + (size_t)(w * 2 + (t & 1)) * TILE_FLOATS;
        const float* wd0 = wbase + t * TILE_D;
#pragma unroll
        for (int blk = 0; blk < 8; ++blk) {
            ulonglong2 xv0 = *reinterpret_cast<const ulonglong2*>(
                xt + li * PITCH + blk * 4);
            ulonglong2 xv1 = *reinterpret_cast<const ulonglong2*>(
                xt + (li + 16) * PITCH + blk * 4);
            const float* wdb = wd0 + blk * 4;
#pragma unroll
            for (int gi = 0; gi < 9; ++gi) {
                ulonglong2 wv = *reinterpret_cast<const ulonglong2*>(wdb + gi * WPITCH);
                fma2(a0[gi], xv0.x, wv.x); fma2(a0[gi], xv0.y, wv.y);
                fma2(a1[gi], xv1.x, wv.x); fma2(a1[gi], xv1.y, wv.y);
            }
            fma2(nr0, xv0.x, xv0.x); fma2(nr0, xv0.y, xv0.y);
            fma2(nr1, xv1.x, xv1.x); fma2(nr1, xv1.y, xv1.y);
        }
        __syncwarp();
        if (t + 2 < NT) {
            uint32_t dst = (t & 1) ? buf1 : buf0;
            const float* src = xrow + (t + 2) * TILE_D;
#pragma unroll
            for (int k = 0; k < 8; ++k) {
                int idx = ln + 32 * k;
                int row = idx >> 3, ch = idx & 7;
                cpasync16(dst + (uint32_t)(row * PITCH + ch * 4) * 4,
                          src + (size_t)row * DD + ch * 4);
            }
        }
        asm volatile("cp.async.commit_group;" ::: "memory");
    }

    // ---------------- epilogue: scores -> smem (tiles dead) ----------------
    __syncthreads();
    float* s_sc   = sm1;                // 17*576 raw scores
    float* s_sim  = sm1 + NG * NP;      // 576
    float* s_mask = s_sim + NP;         // 576

    const int p0 = w * 32 + li, p1 = p0 + 16;
#pragma unroll
    for (int gi = 0; gi < 9; ++gi) {
        int g = h * 9 + gi;
        float v0 = hadd2(a0[gi]), v1 = hadd2(a1[gi]);
        if (g < NG) {
            s_sc[g * NP + p0] = v0;
            s_sc[g * NP + p1] = v1;
        } else {            // g == 17: cls dot-product
            s_cd[p0] = v0;
            s_cd[p1] = v1;
        }
    }
    __syncthreads();
    if (h == 0) {
        // cls-norm factor dropped: positive per-batch constant, ordering-invariant
        s_sim[p0] = s_cd[p0] / fmaxf(sqrtf(hadd2(nr0)), 1e-12f);
        s_sim[p1] = s_cd[p1] / fmaxf(sqrtf(hadd2(nr1)), 1e-12f);
        s_mask[p0] = 1.0f; s_mask[p1] = 1.0f;
    }
    __syncthreads();

    // topk: 10x argmin in warp 0 (tie -> lower index)
    if (tid < 32) {
        for (int k = 0; k < NOCC; ++k) {
            float best = 3.4e38f; int bi = NP;
#pragma unroll
            for (int q = 0; q < NP / 32; ++q) {
                int idx = tid + q * 32;
                float v = s_sim[idx];
                if (v < best || (v == best && idx < bi)) { best = v; bi = idx; }
            }
#pragma unroll
            for (int off = 16; off; off >>= 1) {
                float ov = __shfl_down_sync(0xffffffffu, best, off);
                int   oi = __shfl_down_sync(0xffffffffu, bi, off);
                if (ov < best || (ov == best && oi < bi)) { best = ov; bi = oi; }
            }
            bi = __shfl_sync(0xffffffffu, bi, 0);
            if (tid == 0) { s_sim[bi] = 3.4e38f; s_mask[bi] = 0.0f; }
            __syncwarp();
        }
    }
    __syncthreads();

    // softmax per patch; write attn output + masked attn to g_scores
    {
        const int p = tid;
        const float mk = s_mask[p];
        float tv[NG];
        float m = -3.4e38f;
#pragma unroll
        for (int g = 0; g < NG; ++g) {
            tv[g] = s_sc[g * NP + p] * 10.0f;
            m = fmaxf(m, tv[g]);
        }
        float ssum = 0.f;
#pragma unroll
        for (int g = 0; g < NG; ++g) { tv[g] = __expf(tv[g] - m); ssum += tv[g]; }
        const float inv = 1.0f / ssum;
        float* oat = out + (size_t)NB * NGC * DD + (size_t)b * NG * NP;
#pragma unroll
        for (int g = 0; g < NG; ++g) {
            float a = tv[g] * inv;
            oat[g * NP + p] = (mk != 0.f) ? a : (1.0f / 17.0f);
            g_scores[((size_t)b * NG + g) * NP + p] = (mk != 0.f) ? a : 0.f;
        }
    }
}

// ======================= K3: group features + cls =========================
// grid (NB, 3), block 256, 3 CTAs/SM. Thread owns column d = by*256+tid.
// smem: masked attn [17][576] = 39168 B.
extern __shared__ float sm3[];

__global__ void __launch_bounds__(256, 3)
k3_features(const float* __restrict__ x, float* __restrict__ out) {
    const int b   = blockIdx.x;
    const int tid = threadIdx.x;
    const int d   = blockIdx.y * 256 + tid;
    float* s_at = sm3;

    for (int i = tid; i < NG * NP; i += 256)
        s_at[i] = g_scores[(size_t)b * NG * NP + i];
    __syncthreads();

    const size_t xb = (size_t)b * NTOK * DD;
    const float* xp = x + xb + DD + d;
    ull acc[NG];
#pragma unroll
    for (int g = 0; g < NG; ++g) acc[g] = 0ull;

    float A0 = xp[0], A1 = xp[(size_t)1 * DD], A2 = xp[(size_t)2 * DD], A3 = xp[(size_t)3 * DD];
    float B0 = xp[(size_t)4 * DD], B1 = xp[(size_t)5 * DD], B2 = xp[(size_t)6 * DD], B3 = xp[(size_t)7 * DD];

#pragma unroll 2
    for (int s = 0; s < NP / 4; ++s) {
        float c0, c1, c2, c3;
        if ((s & 1) == 0) {
            c0 = A0; c1 = A1; c2 = A2; c3 = A3;
            if (s + 2 < NP / 4) {
                A0 = xp[(size_t)(4 * s +  8) * DD]; A1 = xp[(size_t)(4 * s +  9) * DD];
                A2 = xp[(size_t)(4 * s + 10) * DD]; A3 = xp[(size_t)(4 * s + 11) * DD];
            }
        } else {
            c0 = B0; c1 = B1; c2 = B2; c3 = B3;
            if (s + 2 < NP / 4) {
                B0 = xp[(size_t)(4 * s +  8) * DD]; B1 = xp[(size_t)(4 * s +  9) * DD];
                B2 = xp[(size_t)(4 * s + 10) * DD]; B3 = xp[(size_t)(4 * s + 11) * DD];
            }
        }
        ull x01 = pk2(c0, c1), x23 = pk2(c2, c3);
        const float* ap = s_at + 4 * s;
#pragma unroll
        for (int g = 0; g < NG; ++g) {
            ulonglong2 at = *reinterpret_cast<const ulonglong2*>(ap + g * NP);
            fma2(acc[g], x01, at.x);
            fma2(acc[g], x23, at.y);
        }
    }

    float* ob = out + (size_t)b * NGC * DD;
    ob[d] = x[xb + d];                        // feats[b][0][d] = cls
#pragma unroll
    for (int g = 0; g < NG; ++g)
        ob[(size_t)(1 + g) * DD + d] = hadd2(acc[g]);
}

extern "C" void kernel_launch(void* const* d_in, const int* in_sizes, int n_in,
                              void* d_out, int out_size) {
    const float* x  = (const float*)d_in[0];
    const float* gw = (const float*)d_in[1];
    float* out = (float*)d_out;

    static bool inited = false;
    if (!inited) {
        cudaFuncSetAttribute(k1_scores, cudaFuncAttributeMaxDynamicSharedMemorySize,
                             K1_SMEM_FLOATS * 4);
        cudaFuncSetAttribute(k3_features, cudaFuncAttributeMaxDynamicSharedMemorySize,
                             NG * NP * 4);
        inited = true;
    }

    k1_scores<<<NB, K1_THREADS, K1_SMEM_FLOATS * 4>>>(x, gw, out);
    k3_features<<<dim3(NB, 3), 256, NG * NP * 4>>>(x, out);
}